// round 1
// baseline (speedup 1.0000x reference)
#include <cuda_runtime.h>
#include <cuda_bf16.h>
#include <math.h>

// Problem constants
#define BB   16
#define NN   512
#define DD   256
#define DI_  512
#define SS   16
#define RR   16
#define HH   512
#define EE   10
#define KCH  3
#define PP   96
#define BN   (BB*NN)   // 8192

// ---------------------------------------------------------------------------
// Scratch arena (single __device__ symbol; sub-buffers carved on host)
// ---------------------------------------------------------------------------
__device__ float g_scratch[143700000];  // ~575 MB

// ---------------------------------------------------------------------------
// Generic fp32 tiled GEMM: C(M,N) = A(M,K) @ B(K,N) (+bias)(silu)(accum)
// 128x128 block tile, TK=8, 256 threads, 8x8 per-thread microtile.
// Requires K % 8 == 0, N % 4 == 0 (true for all uses). Batched via gridDim.z.
// ---------------------------------------------------------------------------
template<bool BIAS, bool DOSILU, bool ACCUM>
__global__ void gemm_k(const float* __restrict__ A, const float* __restrict__ Bm,
                       const float* __restrict__ bias, float* __restrict__ C,
                       int M, int N, int K, long batA, long batB, long batC)
{
    A  += (long)blockIdx.z * batA;
    Bm += (long)blockIdx.z * batB;
    C  += (long)blockIdx.z * batC;

    __shared__ float As[8][128];
    __shared__ float Bs[8][132];

    const int t  = threadIdx.x;
    const int tx = t & 15, ty = t >> 4;
    const int m0 = blockIdx.y * 128, n0 = blockIdx.x * 128;
    const int arow = t >> 1, acol = (t & 1) << 2;
    const int brow = t >> 5, bcol = (t & 31) << 2;

    float acc[8][8];
#pragma unroll
    for (int i = 0; i < 8; i++)
#pragma unroll
        for (int j = 0; j < 8; j++) acc[i][j] = 0.f;

    for (int k0 = 0; k0 < K; k0 += 8) {
        float4 av = make_float4(0.f, 0.f, 0.f, 0.f);
        if (m0 + arow < M)
            av = *reinterpret_cast<const float4*>(A + (long)(m0 + arow) * K + (k0 + acol));
        As[acol + 0][arow] = av.x;
        As[acol + 1][arow] = av.y;
        As[acol + 2][arow] = av.z;
        As[acol + 3][arow] = av.w;

        float4 bv = make_float4(0.f, 0.f, 0.f, 0.f);
        if (n0 + bcol + 3 < N) {
            bv = *reinterpret_cast<const float4*>(Bm + (long)(k0 + brow) * N + (n0 + bcol));
        } else if (n0 + bcol < N) {
            const float* bp = Bm + (long)(k0 + brow) * N;
            float tmp[4] = {0.f, 0.f, 0.f, 0.f};
#pragma unroll
            for (int c = 0; c < 4; c++)
                if (n0 + bcol + c < N) tmp[c] = bp[n0 + bcol + c];
            bv = make_float4(tmp[0], tmp[1], tmp[2], tmp[3]);
        }
        Bs[brow][bcol + 0] = bv.x;
        Bs[brow][bcol + 1] = bv.y;
        Bs[brow][bcol + 2] = bv.z;
        Bs[brow][bcol + 3] = bv.w;

        __syncthreads();

#pragma unroll
        for (int kk = 0; kk < 8; kk++) {
            float a[8], bb[8];
            *(float4*)&a[0]  = *(const float4*)&As[kk][ty * 8];
            *(float4*)&a[4]  = *(const float4*)&As[kk][ty * 8 + 4];
            *(float4*)&bb[0] = *(const float4*)&Bs[kk][tx * 8];
            *(float4*)&bb[4] = *(const float4*)&Bs[kk][tx * 8 + 4];
#pragma unroll
            for (int i = 0; i < 8; i++)
#pragma unroll
                for (int j = 0; j < 8; j++)
                    acc[i][j] = fmaf(a[i], bb[j], acc[i][j]);
        }
        __syncthreads();
    }

#pragma unroll
    for (int i = 0; i < 8; i++) {
        int row = m0 + ty * 8 + i;
        if (row >= M) continue;
#pragma unroll
        for (int j = 0; j < 8; j++) {
            int col = n0 + tx * 8 + j;
            if (col >= N) continue;
            float v = acc[i][j];
            if (BIAS)   v += bias[col];
            if (DOSILU) v = v / (1.f + expf(-v));
            long idx = (long)row * N + col;
            if (ACCUM) C[idx] += v;
            else       C[idx] = v;
        }
    }
}

// ---------------------------------------------------------------------------
// LayerNorm over D=256 (one warp per row)
// ---------------------------------------------------------------------------
__global__ void ln_k(const float* __restrict__ x, float* __restrict__ o,
                     const float* __restrict__ g, const float* __restrict__ b)
{
    int warp = threadIdx.x >> 5, lane = threadIdx.x & 31;
    long row = (long)blockIdx.x * 8 + warp;
    const float* xr = x + row * 256;
    float v[8];
    float s = 0.f, s2 = 0.f;
#pragma unroll
    for (int i = 0; i < 8; i++) {
        v[i] = xr[lane + i * 32];
        s  += v[i];
        s2 += v[i] * v[i];
    }
#pragma unroll
    for (int o2 = 16; o2 > 0; o2 >>= 1) {
        s  += __shfl_xor_sync(0xffffffffu, s,  o2);
        s2 += __shfl_xor_sync(0xffffffffu, s2, o2);
    }
    float mean = s * (1.f / 256.f);
    float var  = s2 * (1.f / 256.f) - mean * mean;
    float inv  = rsqrtf(var + 1e-5f);
#pragma unroll
    for (int i = 0; i < 8; i++) {
        int c = lane + i * 32;
        o[row * 256 + c] = (v[i] - mean) * inv * g[c] + b[c];
    }
}

// ---------------------------------------------------------------------------
// Depthwise causal conv (kernel 4) + SiLU. xi lives in cols [0,512) of xiz.
// ---------------------------------------------------------------------------
__global__ void conv_k(const float* __restrict__ xiz, const float* __restrict__ cw,
                       const float* __restrict__ cb, float* __restrict__ xc)
{
    long idx = (long)blockIdx.x * 256 + threadIdx.x;  // BN*512
    int  di  = (int)(idx & 511);
    long bl  = idx >> 9;
    int  l   = (int)(bl & 511);
    long brow = bl - l;  // b*512
    float acc = cb[di];
#pragma unroll
    for (int j = 0; j < 4; j++) {
        int lp = l - 3 + j;
        if (lp >= 0)
            acc = fmaf(xiz[(brow + lp) * 1024 + di], cw[di * 4 + j], acc);
    }
    float sg = 1.f / (1.f + expf(-acc));
    xc[idx] = acc * sg;
}

// ---------------------------------------------------------------------------
// dt = softplus(dbc[:, :16] @ W_dt + b_dt)
// ---------------------------------------------------------------------------
__global__ void dt_k(const float* __restrict__ dbc, const float* __restrict__ Wd,
                     const float* __restrict__ bd, float* __restrict__ dt)
{
    long idx = (long)blockIdx.x * 256 + threadIdx.x;  // BN*512
    int  di  = (int)(idx & 511);
    long bl  = idx >> 9;
    float a = bd[di];
    const float* dr = dbc + bl * 48;
#pragma unroll
    for (int r = 0; r < 16; r++)
        a = fmaf(dr[r], Wd[r * 512 + di], a);
    dt[idx] = (a > 20.f) ? a : log1pf(expf(a));
}

// ---------------------------------------------------------------------------
// Selective scan. Thread per (b, di, s). 16-lane shuffle reduce for the
// C-contraction. Adds the D_skip term. Output y[b,l,di].
// ---------------------------------------------------------------------------
__global__ void scan_k(const float* __restrict__ dt, const float* __restrict__ xc,
                       const float* __restrict__ dbc, const float* __restrict__ negA,
                       const float* __restrict__ Dp, float* __restrict__ y)
{
    int gid = blockIdx.x * 256 + threadIdx.x;  // B*DI*S = 131072
    int s   = gid & 15;
    int bdi = gid >> 4;
    int di  = bdi & 511;
    int b   = bdi >> 9;
    float na = negA[di * 16 + s];
    float dp = Dp[di];
    float h  = 0.f;
    long base = (long)b * 512;
    for (int l = 0; l < 512; l++) {
        long bl   = base + l;
        float dtv = dt[bl * 512 + di];
        float xcv = xc[bl * 512 + di];
        float bm  = dbc[bl * 48 + 16 + s];
        float cm  = dbc[bl * 48 + 32 + s];
        float dA  = expf(dtv * na);
        h = fmaf(dA, h, dtv * xcv * bm);
        float p = h * cm;
        p += __shfl_down_sync(0xffffffffu, p, 8, 16);
        p += __shfl_down_sync(0xffffffffu, p, 4, 16);
        p += __shfl_down_sync(0xffffffffu, p, 2, 16);
        p += __shfl_down_sync(0xffffffffu, p, 1, 16);
        if (s == 0) y[bl * 512 + di] = p + xcv * dp;
    }
}

// ---------------------------------------------------------------------------
// y *= silu(z)  (z in cols [512,1024) of xiz)
// ---------------------------------------------------------------------------
__global__ void gate_k(float* __restrict__ y, const float* __restrict__ xiz)
{
    long idx = (long)blockIdx.x * 256 + threadIdx.x;  // BN*512
    int  di  = (int)(idx & 511);
    long bl  = idx >> 9;
    float z  = xiz[bl * 1024 + 512 + di];
    y[idx] *= z / (1.f + expf(-z));
}

// ---------------------------------------------------------------------------
// Flip along L
// ---------------------------------------------------------------------------
__global__ void flip_k(const float* __restrict__ in, float* __restrict__ out)
{
    long idx = (long)blockIdx.x * 256 + threadIdx.x;  // BN*256
    int  d   = (int)(idx & 255);
    long bl  = idx >> 8;
    int  l   = (int)(bl & 511);
    long b   = bl >> 9;
    out[idx] = in[((b * 512) + (511 - l)) * 256 + d];
}

// ---------------------------------------------------------------------------
// x += t (rev==0) or x += flip(t) (rev==1)
// ---------------------------------------------------------------------------
__global__ void accum_k(float* __restrict__ x, const float* __restrict__ t, int rev)
{
    long idx = (long)blockIdx.x * 256 + threadIdx.x;  // BN*256
    if (!rev) { x[idx] += t[idx]; return; }
    int  d  = (int)(idx & 255);
    long bl = idx >> 8;
    int  l  = (int)(bl & 511);
    long b  = bl >> 9;
    x[idx] += t[((b * 512) + (511 - l)) * 256 + d];
}

// ---------------------------------------------------------------------------
// negA = -exp(A_log)   (both directions at once, 16384 elems)
// ---------------------------------------------------------------------------
__global__ void nega_k(const float* __restrict__ Alog, float* __restrict__ negA)
{
    int i = blockIdx.x * 256 + threadIdx.x;
    negA[i] = -expf(Alog[i]);
}

// ---------------------------------------------------------------------------
// nbias[n,o] = sum_e emb[n,e] * bias_pool[e,o]
// ---------------------------------------------------------------------------
__global__ void nbias_k(const float* __restrict__ emb, const float* __restrict__ bp,
                        float* __restrict__ nb)
{
    int i = blockIdx.x * 256 + threadIdx.x;  // 512*256
    int o = i & 255;
    int n = i >> 8;
    float a = 0.f;
#pragma unroll
    for (int e = 0; e < 10; e++)
        a = fmaf(emb[n * 10 + e], bp[e * 256 + o], a);
    nb[i] = a;
}

// ---------------------------------------------------------------------------
// sup = row-softmax(relu(emb @ emb^T)), one block per row
// ---------------------------------------------------------------------------
__global__ void sup_k(const float* __restrict__ emb, float* __restrict__ sup)
{
    int n = blockIdx.x;
    __shared__ float en[10];
    __shared__ float row[512];
    __shared__ float red[8];
    int t = threadIdx.x;  // 256
    if (t < 10) en[t] = emb[n * 10 + t];
    __syncthreads();

    float lmax = 0.f;
    for (int m = t; m < 512; m += 256) {
        float d = 0.f;
#pragma unroll
        for (int e = 0; e < 10; e++) d = fmaf(en[e], emb[m * 10 + e], d);
        d = fmaxf(d, 0.f);
        row[m] = d;
        lmax = fmaxf(lmax, d);
    }
#pragma unroll
    for (int o = 16; o > 0; o >>= 1)
        lmax = fmaxf(lmax, __shfl_xor_sync(0xffffffffu, lmax, o));
    if ((t & 31) == 0) red[t >> 5] = lmax;
    __syncthreads();
    float bmax = fmaxf(fmaxf(fmaxf(red[0], red[1]), fmaxf(red[2], red[3])),
                       fmaxf(fmaxf(red[4], red[5]), fmaxf(red[6], red[7])));
    __syncthreads();

    float lsum = 0.f;
    for (int m = t; m < 512; m += 256) {
        float e = expf(row[m] - bmax);
        row[m] = e;
        lsum += e;
    }
#pragma unroll
    for (int o = 16; o > 0; o >>= 1)
        lsum += __shfl_xor_sync(0xffffffffu, lsum, o);
    if ((t & 31) == 0) red[t >> 5] = lsum;
    __syncthreads();
    float bsum = red[0] + red[1] + red[2] + red[3] + red[4] + red[5] + red[6] + red[7];
    float inv = 1.f / bsum;
    for (int m = t; m < 512; m += 256)
        sup[n * 512 + m] = row[m] * inv;
}

// ---------------------------------------------------------------------------
// cheb2 = 2*cheb2 - I
// ---------------------------------------------------------------------------
__global__ void chebfix_k(float* __restrict__ c2)
{
    int i = blockIdx.x * 256 + threadIdx.x;  // 512*512
    float v = 2.f * c2[i];
    if ((i >> 9) == (i & 511)) v -= 1.f;
    c2[i] = v;
}

// ---------------------------------------------------------------------------
// xg[b,0,:,:] = x[b,:,:]
// ---------------------------------------------------------------------------
__global__ void xg0_k(const float* __restrict__ x, float* __restrict__ xg)
{
    long i = (long)blockIdx.x * 256 + threadIdx.x;  // B*N*D
    long nd = i % (512 * 256);
    long b  = i / (512 * 256);
    xg[(b * 3) * 512 * 256 + nd] = x[i];
}

// ---------------------------------------------------------------------------
// Wn[n, j] = sum_e emb[n,e] * wp[e, j],  j over K*D*D = 196608 (float4-wide)
// ---------------------------------------------------------------------------
__global__ void wn_k(const float* __restrict__ emb, const float* __restrict__ wp,
                     float* __restrict__ Wn)
{
    long i4 = (long)blockIdx.x * 256 + threadIdx.x;  // 512 * 49152
    long j4 = i4 % 49152;
    long n  = i4 / 49152;
    const float4* w4 = (const float4*)wp;
    const float* en = emb + n * 10;
    float4 a = make_float4(0.f, 0.f, 0.f, 0.f);
#pragma unroll
    for (int e = 0; e < 10; e++) {
        float4 w = w4[(long)e * 49152 + j4];
        float ev = en[e];
        a.x = fmaf(ev, w.x, a.x);
        a.y = fmaf(ev, w.y, a.y);
        a.z = fmaf(ev, w.z, a.z);
        a.w = fmaf(ev, w.w, a.w);
    }
    ((float4*)Wn)[i4] = a;
}

// ---------------------------------------------------------------------------
// x2[b,n,o] = sum_{kd} xg[b,k,n,d] * Wn[n,kd,o] + nbias[n,o]
// One block per node n. A-tile (16 x 768) in 48KB smem.
// ---------------------------------------------------------------------------
__global__ void x2_k(const float* __restrict__ xg, const float* __restrict__ Wn,
                     const float* __restrict__ nbias, float* __restrict__ x2)
{
    __shared__ float At[16][768];
    int n = blockIdx.x;
    int t = threadIdx.x;  // 256

    for (int i = t; i < 16 * 768; i += 256) {
        int b  = i / 768;
        int kd = i % 768;
        int k  = kd >> 8;
        int d  = kd & 255;
        At[b][kd] = xg[(((long)(b * 3 + k)) * 512 + n) * 256 + d];
    }
    __syncthreads();

    int o = t;
    float bias = nbias[n * 256 + o];
    float acc[16];
#pragma unroll
    for (int b = 0; b < 16; b++) acc[b] = bias;

    const float* w = Wn + (long)n * 196608 + o;
    for (int kd = 0; kd < 768; kd += 4) {
        float w0 = w[(long)(kd + 0) * 256];
        float w1 = w[(long)(kd + 1) * 256];
        float w2 = w[(long)(kd + 2) * 256];
        float w3 = w[(long)(kd + 3) * 256];
#pragma unroll
        for (int b = 0; b < 16; b++) {
            float4 a = *(const float4*)&At[b][kd];
            acc[b] = fmaf(a.x, w0, acc[b]);
            acc[b] = fmaf(a.y, w1, acc[b]);
            acc[b] = fmaf(a.z, w2, acc[b]);
            acc[b] = fmaf(a.w, w3, acc[b]);
        }
    }
#pragma unroll
    for (int b = 0; b < 16; b++)
        x2[((long)b * 512 + n) * 256 + o] = acc[b];
}

// ---------------------------------------------------------------------------
// Host driver
// ---------------------------------------------------------------------------
extern "C" void kernel_launch(void* const* d_in, const int* in_sizes, int n_in,
                              void* d_out, int out_size)
{
    float* base = nullptr;
    cudaGetSymbolAddress((void**)&base, g_scratch);

    const float* input = (const float*)d_in[0];
    const float* ln1g  = (const float*)d_in[1];
    const float* ln1b  = (const float*)d_in[2];
    const float* ln2g  = (const float*)d_in[3];
    const float* ln2b  = (const float*)d_in[4];
    const float* Win   = (const float*)d_in[5];   // (2,256,1024)
    const float* convw = (const float*)d_in[6];   // (2,512,4)
    const float* convb = (const float*)d_in[7];   // (2,512)
    const float* Wx    = (const float*)d_in[8];   // (2,512,48)
    const float* Wd    = (const float*)d_in[9];   // (2,16,512)
    const float* bd    = (const float*)d_in[10];  // (2,512)
    const float* Alog  = (const float*)d_in[11];  // (2,512,16)
    const float* Dsk   = (const float*)d_in[12];  // (2,512)
    const float* Wout  = (const float*)d_in[13];  // (2,512,256)
    const float* fW1   = (const float*)d_in[14];  // (256,512)
    const float* fb1   = (const float*)d_in[15];
    const float* fW2   = (const float*)d_in[16];  // (512,256)
    const float* fb2   = (const float*)d_in[17];
    const float* emb   = (const float*)d_in[18];  // (512,10)
    const float* wpool = (const float*)d_in[19];  // (10,3,256,256)
    const float* bpool = (const float*)d_in[20];  // (10,256)
    const float* Wproj = (const float*)d_in[21];  // (256,96)
    const float* bproj = (const float*)d_in[22];  // (96)
    float* out = (float*)d_out;

    // carve scratch
    long off = 0;
    auto carve = [&](long nfl) { float* p = base + off; off += nfl; return p; };
    float* X    = carve((long)BN * 256);
    float* XN   = carve((long)BN * 256);
    float* XNF  = carve((long)BN * 256);
    float* XIZ  = carve((long)BN * 1024);
    float* XC   = carve((long)BN * 512);
    float* DBC  = carve((long)BN * 48);
    float* DT   = carve((long)BN * 512);
    float* Y    = carve((long)BN * 512);
    float* TMP  = carve((long)BN * 256);
    float* FFN  = carve((long)BN * 512);
    float* NEGA = carve(2L * 512 * 16);
    float* SUP  = carve(512L * 512);
    float* CH2  = carve(512L * 512);
    float* XG   = carve(16L * 3 * 512 * 256);
    float* NB   = carve(512L * 256);
    float* X2   = carve((long)BN * 256);
    float* WN   = carve(512L * 3 * 256 * 256);

    cudaMemcpyAsync(X, input, sizeof(float) * (long)BN * 256, cudaMemcpyDeviceToDevice);
    nega_k<<<64, 256>>>(Alog, NEGA);
    nbias_k<<<512, 256>>>(emb, bpool, NB);

    for (int layer = 0; layer < 3; layer++) {
        ln_k<<<1024, 256>>>(X, XN, ln1g, ln1b);
        flip_k<<<8192, 256>>>(XN, XNF);

        for (int dir = 0; dir < 2; dir++) {
            const float* src = dir ? XNF : XN;
            gemm_k<false, false, false><<<dim3(8, 64, 1), 256>>>(
                src, Win + (long)dir * 256 * 1024, nullptr, XIZ, 8192, 1024, 256, 0, 0, 0);
            conv_k<<<16384, 256>>>(XIZ, convw + dir * 512 * 4, convb + dir * 512, XC);
            gemm_k<false, false, false><<<dim3(1, 64, 1), 256>>>(
                XC, Wx + (long)dir * 512 * 48, nullptr, DBC, 8192, 48, 512, 0, 0, 0);
            dt_k<<<16384, 256>>>(DBC, Wd + dir * 16 * 512, bd + dir * 512, DT);
            scan_k<<<512, 256>>>(DT, XC, DBC, NEGA + dir * 8192, Dsk + dir * 512, Y);
            gate_k<<<16384, 256>>>(Y, XIZ);
            gemm_k<false, false, false><<<dim3(2, 64, 1), 256>>>(
                Y, Wout + (long)dir * 512 * 256, nullptr, TMP, 8192, 256, 512, 0, 0, 0);
            accum_k<<<8192, 256>>>(X, TMP, dir);
        }

        ln_k<<<1024, 256>>>(X, XN, ln2g, ln2b);
        gemm_k<true, true, false><<<dim3(4, 64, 1), 256>>>(
            XN, fW1, fb1, FFN, 8192, 512, 256, 0, 0, 0);
        gemm_k<true, false, true><<<dim3(2, 64, 1), 256>>>(
            FFN, fW2, fb2, X, 8192, 256, 512, 0, 0, 0);
    }

    // Graph section
    sup_k<<<512, 256>>>(emb, SUP);
    gemm_k<false, false, false><<<dim3(4, 4, 1), 256>>>(
        SUP, SUP, nullptr, CH2, 512, 512, 512, 0, 0, 0);
    chebfix_k<<<1024, 256>>>(CH2);

    xg0_k<<<8192, 256>>>(X, XG);
    gemm_k<false, false, false><<<dim3(2, 4, 16), 256>>>(
        SUP, X, nullptr, XG + 1L * 512 * 256, 512, 256, 512,
        0, 512L * 256, 3L * 512 * 256);
    gemm_k<false, false, false><<<dim3(2, 4, 16), 256>>>(
        CH2, X, nullptr, XG + 2L * 512 * 256, 512, 256, 512,
        0, 512L * 256, 3L * 512 * 256);

    wn_k<<<98304, 256>>>(emb, wpool, WN);
    x2_k<<<512, 256>>>(XG, WN, NB, X2);

    gemm_k<true, false, false><<<dim3(1, 64, 1), 256>>>(
        X2, Wproj, bproj, out, 8192, 96, 256, 0, 0, 0);
}

// round 2
// speedup vs baseline: 1.0009x; 1.0009x over previous
#include <cuda_runtime.h>
#include <cuda_bf16.h>
#include <math.h>

// Problem constants
#define BB   16
#define NN   512
#define DD   256
#define DI_  512
#define SS   16
#define RR   16
#define HH   512
#define EE   10
#define KCH  3
#define PP   96
#define BN   (BB*NN)   // 8192

// ---------------------------------------------------------------------------
// Scratch arena (single __device__ symbol; sub-buffers carved on host)
// ---------------------------------------------------------------------------
__device__ float g_scratch[143700000];  // ~575 MB

// ---------------------------------------------------------------------------
// Generic fp32 tiled GEMM: C(M,N) = A(M,K) @ B(K,N) (+bias)(silu)(accum)
// 128x128 block tile, TK=8, 256 threads, 8x8 per-thread microtile.
// Requires K % 8 == 0, N % 4 == 0 (true for all uses). Batched via gridDim.z.
// ---------------------------------------------------------------------------
template<bool BIAS, bool DOSILU, bool ACCUM>
__global__ void gemm_k(const float* __restrict__ A, const float* __restrict__ Bm,
                       const float* __restrict__ bias, float* __restrict__ C,
                       int M, int N, int K, long batA, long batB, long batC)
{
    A  += (long)blockIdx.z * batA;
    Bm += (long)blockIdx.z * batB;
    C  += (long)blockIdx.z * batC;

    __shared__ float As[8][128];
    __shared__ float Bs[8][132];

    const int t  = threadIdx.x;
    const int tx = t & 15, ty = t >> 4;
    const int m0 = blockIdx.y * 128, n0 = blockIdx.x * 128;
    const int arow = t >> 1, acol = (t & 1) << 2;
    const int brow = t >> 5, bcol = (t & 31) << 2;

    float acc[8][8];
#pragma unroll
    for (int i = 0; i < 8; i++)
#pragma unroll
        for (int j = 0; j < 8; j++) acc[i][j] = 0.f;

    for (int k0 = 0; k0 < K; k0 += 8) {
        float4 av = make_float4(0.f, 0.f, 0.f, 0.f);
        if (m0 + arow < M)
            av = *reinterpret_cast<const float4*>(A + (long)(m0 + arow) * K + (k0 + acol));
        As[acol + 0][arow] = av.x;
        As[acol + 1][arow] = av.y;
        As[acol + 2][arow] = av.z;
        As[acol + 3][arow] = av.w;

        float4 bv = make_float4(0.f, 0.f, 0.f, 0.f);
        if (n0 + bcol + 3 < N) {
            bv = *reinterpret_cast<const float4*>(Bm + (long)(k0 + brow) * N + (n0 + bcol));
        } else if (n0 + bcol < N) {
            const float* bp = Bm + (long)(k0 + brow) * N;
            float tmp[4] = {0.f, 0.f, 0.f, 0.f};
#pragma unroll
            for (int c = 0; c < 4; c++)
                if (n0 + bcol + c < N) tmp[c] = bp[n0 + bcol + c];
            bv = make_float4(tmp[0], tmp[1], tmp[2], tmp[3]);
        }
        Bs[brow][bcol + 0] = bv.x;
        Bs[brow][bcol + 1] = bv.y;
        Bs[brow][bcol + 2] = bv.z;
        Bs[brow][bcol + 3] = bv.w;

        __syncthreads();

#pragma unroll
        for (int kk = 0; kk < 8; kk++) {
            float a[8], bb[8];
            *(float4*)&a[0]  = *(const float4*)&As[kk][ty * 8];
            *(float4*)&a[4]  = *(const float4*)&As[kk][ty * 8 + 4];
            *(float4*)&bb[0] = *(const float4*)&Bs[kk][tx * 8];
            *(float4*)&bb[4] = *(const float4*)&Bs[kk][tx * 8 + 4];
#pragma unroll
            for (int i = 0; i < 8; i++)
#pragma unroll
                for (int j = 0; j < 8; j++)
                    acc[i][j] = fmaf(a[i], bb[j], acc[i][j]);
        }
        __syncthreads();
    }

#pragma unroll
    for (int i = 0; i < 8; i++) {
        int row = m0 + ty * 8 + i;
        if (row >= M) continue;
#pragma unroll
        for (int j = 0; j < 8; j++) {
            int col = n0 + tx * 8 + j;
            if (col >= N) continue;
            float v = acc[i][j];
            if (BIAS)   v += bias[col];
            if (DOSILU) v = v / (1.f + expf(-v));
            long idx = (long)row * N + col;
            if (ACCUM) C[idx] += v;
            else       C[idx] = v;
        }
    }
}

// ---------------------------------------------------------------------------
// LayerNorm over D=256 (one warp per row)
// ---------------------------------------------------------------------------
__global__ void ln_k(const float* __restrict__ x, float* __restrict__ o,
                     const float* __restrict__ g, const float* __restrict__ b)
{
    int warp = threadIdx.x >> 5, lane = threadIdx.x & 31;
    long row = (long)blockIdx.x * 8 + warp;
    const float* xr = x + row * 256;
    float v[8];
    float s = 0.f, s2 = 0.f;
#pragma unroll
    for (int i = 0; i < 8; i++) {
        v[i] = xr[lane + i * 32];
        s  += v[i];
        s2 += v[i] * v[i];
    }
#pragma unroll
    for (int o2 = 16; o2 > 0; o2 >>= 1) {
        s  += __shfl_xor_sync(0xffffffffu, s,  o2);
        s2 += __shfl_xor_sync(0xffffffffu, s2, o2);
    }
    float mean = s * (1.f / 256.f);
    float var  = s2 * (1.f / 256.f) - mean * mean;
    float inv  = rsqrtf(var + 1e-5f);
#pragma unroll
    for (int i = 0; i < 8; i++) {
        int c = lane + i * 32;
        o[row * 256 + c] = (v[i] - mean) * inv * g[c] + b[c];
    }
}

// ---------------------------------------------------------------------------
// Depthwise causal conv (kernel 4) + SiLU. xi lives in cols [0,512) of xiz.
// ---------------------------------------------------------------------------
__global__ void conv_k(const float* __restrict__ xiz, const float* __restrict__ cw,
                       const float* __restrict__ cb, float* __restrict__ xc)
{
    long idx = (long)blockIdx.x * 256 + threadIdx.x;  // BN*512
    int  di  = (int)(idx & 511);
    long bl  = idx >> 9;
    int  l   = (int)(bl & 511);
    long brow = bl - l;  // b*512
    float acc = cb[di];
#pragma unroll
    for (int j = 0; j < 4; j++) {
        int lp = l - 3 + j;
        if (lp >= 0)
            acc = fmaf(xiz[(brow + lp) * 1024 + di], cw[di * 4 + j], acc);
    }
    float sg = 1.f / (1.f + expf(-acc));
    xc[idx] = acc * sg;
}

// ---------------------------------------------------------------------------
// dt = softplus(dbc[:, :16] @ W_dt + b_dt)
// ---------------------------------------------------------------------------
__global__ void dt_k(const float* __restrict__ dbc, const float* __restrict__ Wd,
                     const float* __restrict__ bd, float* __restrict__ dt)
{
    long idx = (long)blockIdx.x * 256 + threadIdx.x;  // BN*512
    int  di  = (int)(idx & 511);
    long bl  = idx >> 9;
    float a = bd[di];
    const float* dr = dbc + bl * 48;
#pragma unroll
    for (int r = 0; r < 16; r++)
        a = fmaf(dr[r], Wd[r * 512 + di], a);
    dt[idx] = (a > 20.f) ? a : log1pf(expf(a));
}

// ---------------------------------------------------------------------------
// Selective scan. Thread per (b, di, s). 16-lane shuffle reduce for the
// C-contraction. Adds the D_skip term. Output y[b,l,di].
// ---------------------------------------------------------------------------
__global__ void scan_k(const float* __restrict__ dt, const float* __restrict__ xc,
                       const float* __restrict__ dbc, const float* __restrict__ negA,
                       const float* __restrict__ Dp, float* __restrict__ y)
{
    int gid = blockIdx.x * 256 + threadIdx.x;  // B*DI*S = 131072
    int s   = gid & 15;
    int bdi = gid >> 4;
    int di  = bdi & 511;
    int b   = bdi >> 9;
    float na = negA[di * 16 + s];
    float dp = Dp[di];
    float h  = 0.f;
    long base = (long)b * 512;
    for (int l = 0; l < 512; l++) {
        long bl   = base + l;
        float dtv = dt[bl * 512 + di];
        float xcv = xc[bl * 512 + di];
        float bm  = dbc[bl * 48 + 16 + s];
        float cm  = dbc[bl * 48 + 32 + s];
        float dA  = expf(dtv * na);
        h = fmaf(dA, h, dtv * xcv * bm);
        float p = h * cm;
        p += __shfl_down_sync(0xffffffffu, p, 8, 16);
        p += __shfl_down_sync(0xffffffffu, p, 4, 16);
        p += __shfl_down_sync(0xffffffffu, p, 2, 16);
        p += __shfl_down_sync(0xffffffffu, p, 1, 16);
        if (s == 0) y[bl * 512 + di] = p + xcv * dp;
    }
}

// ---------------------------------------------------------------------------
// y *= silu(z)  (z in cols [512,1024) of xiz)
// ---------------------------------------------------------------------------
__global__ void gate_k(float* __restrict__ y, const float* __restrict__ xiz)
{
    long idx = (long)blockIdx.x * 256 + threadIdx.x;  // BN*512
    int  di  = (int)(idx & 511);
    long bl  = idx >> 9;
    float z  = xiz[bl * 1024 + 512 + di];
    y[idx] *= z / (1.f + expf(-z));
}

// ---------------------------------------------------------------------------
// Flip along L
// ---------------------------------------------------------------------------
__global__ void flip_k(const float* __restrict__ in, float* __restrict__ out)
{
    long idx = (long)blockIdx.x * 256 + threadIdx.x;  // BN*256
    int  d   = (int)(idx & 255);
    long bl  = idx >> 8;
    int  l   = (int)(bl & 511);
    long b   = bl >> 9;
    out[idx] = in[((b * 512) + (511 - l)) * 256 + d];
}

// ---------------------------------------------------------------------------
// x += t (rev==0) or x += flip(t) (rev==1)
// ---------------------------------------------------------------------------
__global__ void accum_k(float* __restrict__ x, const float* __restrict__ t, int rev)
{
    long idx = (long)blockIdx.x * 256 + threadIdx.x;  // BN*256
    if (!rev) { x[idx] += t[idx]; return; }
    int  d  = (int)(idx & 255);
    long bl = idx >> 8;
    int  l  = (int)(bl & 511);
    long b  = bl >> 9;
    x[idx] += t[((b * 512) + (511 - l)) * 256 + d];
}

// ---------------------------------------------------------------------------
// negA = -exp(A_log)   (both directions at once, 16384 elems)
// ---------------------------------------------------------------------------
__global__ void nega_k(const float* __restrict__ Alog, float* __restrict__ negA)
{
    int i = blockIdx.x * 256 + threadIdx.x;
    negA[i] = -expf(Alog[i]);
}

// ---------------------------------------------------------------------------
// nbias[n,o] = sum_e emb[n,e] * bias_pool[e,o]
// ---------------------------------------------------------------------------
__global__ void nbias_k(const float* __restrict__ emb, const float* __restrict__ bp,
                        float* __restrict__ nb)
{
    int i = blockIdx.x * 256 + threadIdx.x;  // 512*256
    int o = i & 255;
    int n = i >> 8;
    float a = 0.f;
#pragma unroll
    for (int e = 0; e < 10; e++)
        a = fmaf(emb[n * 10 + e], bp[e * 256 + o], a);
    nb[i] = a;
}

// ---------------------------------------------------------------------------
// sup = row-softmax(relu(emb @ emb^T)), one block per row
// ---------------------------------------------------------------------------
__global__ void sup_k(const float* __restrict__ emb, float* __restrict__ sup)
{
    int n = blockIdx.x;
    __shared__ float en[10];
    __shared__ float row[512];
    __shared__ float red[8];
    int t = threadIdx.x;  // 256
    if (t < 10) en[t] = emb[n * 10 + t];
    __syncthreads();

    float lmax = 0.f;
    for (int m = t; m < 512; m += 256) {
        float d = 0.f;
#pragma unroll
        for (int e = 0; e < 10; e++) d = fmaf(en[e], emb[m * 10 + e], d);
        d = fmaxf(d, 0.f);
        row[m] = d;
        lmax = fmaxf(lmax, d);
    }
#pragma unroll
    for (int o = 16; o > 0; o >>= 1)
        lmax = fmaxf(lmax, __shfl_xor_sync(0xffffffffu, lmax, o));
    if ((t & 31) == 0) red[t >> 5] = lmax;
    __syncthreads();
    float bmax = fmaxf(fmaxf(fmaxf(red[0], red[1]), fmaxf(red[2], red[3])),
                       fmaxf(fmaxf(red[4], red[5]), fmaxf(red[6], red[7])));
    __syncthreads();

    float lsum = 0.f;
    for (int m = t; m < 512; m += 256) {
        float e = expf(row[m] - bmax);
        row[m] = e;
        lsum += e;
    }
#pragma unroll
    for (int o = 16; o > 0; o >>= 1)
        lsum += __shfl_xor_sync(0xffffffffu, lsum, o);
    if ((t & 31) == 0) red[t >> 5] = lsum;
    __syncthreads();
    float bsum = red[0] + red[1] + red[2] + red[3] + red[4] + red[5] + red[6] + red[7];
    float inv = 1.f / bsum;
    for (int m = t; m < 512; m += 256)
        sup[n * 512 + m] = row[m] * inv;
}

// ---------------------------------------------------------------------------
// cheb2 = 2*cheb2 - I
// ---------------------------------------------------------------------------
__global__ void chebfix_k(float* __restrict__ c2)
{
    int i = blockIdx.x * 256 + threadIdx.x;  // 512*512
    float v = 2.f * c2[i];
    if ((i >> 9) == (i & 511)) v -= 1.f;
    c2[i] = v;
}

// ---------------------------------------------------------------------------
// xg[b,0,:,:] = x[b,:,:]
// ---------------------------------------------------------------------------
__global__ void xg0_k(const float* __restrict__ x, float* __restrict__ xg)
{
    long i = (long)blockIdx.x * 256 + threadIdx.x;  // B*N*D
    long nd = i % (512 * 256);
    long b  = i / (512 * 256);
    xg[(b * 3) * 512 * 256 + nd] = x[i];
}

// ---------------------------------------------------------------------------
// Wn[n, j] = sum_e emb[n,e] * wp[e, j],  j over K*D*D = 196608 (float4-wide)
// ---------------------------------------------------------------------------
__global__ void wn_k(const float* __restrict__ emb, const float* __restrict__ wp,
                     float* __restrict__ Wn)
{
    long i4 = (long)blockIdx.x * 256 + threadIdx.x;  // 512 * 49152
    long j4 = i4 % 49152;
    long n  = i4 / 49152;
    const float4* w4 = (const float4*)wp;
    const float* en = emb + n * 10;
    float4 a = make_float4(0.f, 0.f, 0.f, 0.f);
#pragma unroll
    for (int e = 0; e < 10; e++) {
        float4 w = w4[(long)e * 49152 + j4];
        float ev = en[e];
        a.x = fmaf(ev, w.x, a.x);
        a.y = fmaf(ev, w.y, a.y);
        a.z = fmaf(ev, w.z, a.z);
        a.w = fmaf(ev, w.w, a.w);
    }
    ((float4*)Wn)[i4] = a;
}

// ---------------------------------------------------------------------------
// x2[b,n,o] = sum_{kd} xg[b,k,n,d] * Wn[n,kd,o] + nbias[n,o]
// One block per node n. A-tile (16 x 768) in 48KB smem.
// ---------------------------------------------------------------------------
__global__ void x2_k(const float* __restrict__ xg, const float* __restrict__ Wn,
                     const float* __restrict__ nbias, float* __restrict__ x2)
{
    __shared__ float At[16][768];
    int n = blockIdx.x;
    int t = threadIdx.x;  // 256

    for (int i = t; i < 16 * 768; i += 256) {
        int b  = i / 768;
        int kd = i % 768;
        int k  = kd >> 8;
        int d  = kd & 255;
        At[b][kd] = xg[(((long)(b * 3 + k)) * 512 + n) * 256 + d];
    }
    __syncthreads();

    int o = t;
    float bias = nbias[n * 256 + o];
    float acc[16];
#pragma unroll
    for (int b = 0; b < 16; b++) acc[b] = bias;

    const float* w = Wn + (long)n * 196608 + o;
    for (int kd = 0; kd < 768; kd += 4) {
        float w0 = w[(long)(kd + 0) * 256];
        float w1 = w[(long)(kd + 1) * 256];
        float w2 = w[(long)(kd + 2) * 256];
        float w3 = w[(long)(kd + 3) * 256];
#pragma unroll
        for (int b = 0; b < 16; b++) {
            float4 a = *(const float4*)&At[b][kd];
            acc[b] = fmaf(a.x, w0, acc[b]);
            acc[b] = fmaf(a.y, w1, acc[b]);
            acc[b] = fmaf(a.z, w2, acc[b]);
            acc[b] = fmaf(a.w, w3, acc[b]);
        }
    }
#pragma unroll
    for (int b = 0; b < 16; b++)
        x2[((long)b * 512 + n) * 256 + o] = acc[b];
}

// ---------------------------------------------------------------------------
// Host driver
// ---------------------------------------------------------------------------
extern "C" void kernel_launch(void* const* d_in, const int* in_sizes, int n_in,
                              void* d_out, int out_size)
{
    float* base = nullptr;
    cudaGetSymbolAddress((void**)&base, g_scratch);

    const float* input = (const float*)d_in[0];
    const float* ln1g  = (const float*)d_in[1];
    const float* ln1b  = (const float*)d_in[2];
    const float* ln2g  = (const float*)d_in[3];
    const float* ln2b  = (const float*)d_in[4];
    const float* Win   = (const float*)d_in[5];   // (2,256,1024)
    const float* convw = (const float*)d_in[6];   // (2,512,4)
    const float* convb = (const float*)d_in[7];   // (2,512)
    const float* Wx    = (const float*)d_in[8];   // (2,512,48)
    const float* Wd    = (const float*)d_in[9];   // (2,16,512)
    const float* bd    = (const float*)d_in[10];  // (2,512)
    const float* Alog  = (const float*)d_in[11];  // (2,512,16)
    const float* Dsk   = (const float*)d_in[12];  // (2,512)
    const float* Wout  = (const float*)d_in[13];  // (2,512,256)
    const float* fW1   = (const float*)d_in[14];  // (256,512)
    const float* fb1   = (const float*)d_in[15];
    const float* fW2   = (const float*)d_in[16];  // (512,256)
    const float* fb2   = (const float*)d_in[17];
    const float* emb   = (const float*)d_in[18];  // (512,10)
    const float* wpool = (const float*)d_in[19];  // (10,3,256,256)
    const float* bpool = (const float*)d_in[20];  // (10,256)
    const float* Wproj = (const float*)d_in[21];  // (256,96)
    const float* bproj = (const float*)d_in[22];  // (96)
    float* out = (float*)d_out;

    // carve scratch
    long off = 0;
    auto carve = [&](long nfl) { float* p = base + off; off += nfl; return p; };
    float* X    = carve((long)BN * 256);
    float* XN   = carve((long)BN * 256);
    float* XNF  = carve((long)BN * 256);
    float* XIZ  = carve((long)BN * 1024);
    float* XC   = carve((long)BN * 512);
    float* DBC  = carve((long)BN * 48);
    float* DT   = carve((long)BN * 512);
    float* Y    = carve((long)BN * 512);
    float* TMP  = carve((long)BN * 256);
    float* FFN  = carve((long)BN * 512);
    float* NEGA = carve(2L * 512 * 16);
    float* SUP  = carve(512L * 512);
    float* CH2  = carve(512L * 512);
    float* XG   = carve(16L * 3 * 512 * 256);
    float* NB   = carve(512L * 256);
    float* X2   = carve((long)BN * 256);
    float* WN   = carve(512L * 3 * 256 * 256);

    cudaMemcpyAsync(X, input, sizeof(float) * (long)BN * 256, cudaMemcpyDeviceToDevice);
    nega_k<<<64, 256>>>(Alog, NEGA);
    nbias_k<<<512, 256>>>(emb, bpool, NB);

    for (int layer = 0; layer < 3; layer++) {
        ln_k<<<1024, 256>>>(X, XN, ln1g, ln1b);
        flip_k<<<8192, 256>>>(XN, XNF);

        for (int dir = 0; dir < 2; dir++) {
            const float* src = dir ? XNF : XN;
            gemm_k<false, false, false><<<dim3(8, 64, 1), 256>>>(
                src, Win + (long)dir * 256 * 1024, nullptr, XIZ, 8192, 1024, 256, 0, 0, 0);
            conv_k<<<16384, 256>>>(XIZ, convw + dir * 512 * 4, convb + dir * 512, XC);
            gemm_k<false, false, false><<<dim3(1, 64, 1), 256>>>(
                XC, Wx + (long)dir * 512 * 48, nullptr, DBC, 8192, 48, 512, 0, 0, 0);
            dt_k<<<16384, 256>>>(DBC, Wd + dir * 16 * 512, bd + dir * 512, DT);
            scan_k<<<512, 256>>>(DT, XC, DBC, NEGA + dir * 8192, Dsk + dir * 512, Y);
            gate_k<<<16384, 256>>>(Y, XIZ);
            gemm_k<false, false, false><<<dim3(2, 64, 1), 256>>>(
                Y, Wout + (long)dir * 512 * 256, nullptr, TMP, 8192, 256, 512, 0, 0, 0);
            accum_k<<<8192, 256>>>(X, TMP, dir);
        }

        ln_k<<<1024, 256>>>(X, XN, ln2g, ln2b);
        gemm_k<true, true, false><<<dim3(4, 64, 1), 256>>>(
            XN, fW1, fb1, FFN, 8192, 512, 256, 0, 0, 0);
        gemm_k<true, false, true><<<dim3(2, 64, 1), 256>>>(
            FFN, fW2, fb2, X, 8192, 256, 512, 0, 0, 0);
    }

    // Graph section
    sup_k<<<512, 256>>>(emb, SUP);
    gemm_k<false, false, false><<<dim3(4, 4, 1), 256>>>(
        SUP, SUP, nullptr, CH2, 512, 512, 512, 0, 0, 0);
    chebfix_k<<<1024, 256>>>(CH2);

    xg0_k<<<8192, 256>>>(X, XG);
    gemm_k<false, false, false><<<dim3(2, 4, 16), 256>>>(
        SUP, X, nullptr, XG + 1L * 512 * 256, 512, 256, 512,
        0, 512L * 256, 3L * 512 * 256);
    gemm_k<false, false, false><<<dim3(2, 4, 16), 256>>>(
        CH2, X, nullptr, XG + 2L * 512 * 256, 512, 256, 512,
        0, 512L * 256, 3L * 512 * 256);

    wn_k<<<98304, 256>>>(emb, wpool, WN);
    x2_k<<<512, 256>>>(XG, WN, NB, X2);

    gemm_k<true, false, false><<<dim3(1, 64, 1), 256>>>(
        X2, Wproj, bproj, out, 8192, 96, 256, 0, 0, 0);
}